// round 3
// baseline (speedup 1.0000x reference)
#include <cuda_runtime.h>

// CliffordInteractionExpert — p=3,q=1,r=0, ALG=16, shifts {1,2,4}
// x: (B=8, T=4096, D=1024) fp32; out same.
//
// Per (b,t):
//   gate = sigmoid(dot(x_row, gate_w) + gate_b)
//   for s in {1,2,4}: c = x_row - x[(t-s) mod T]
//     scalar_s = sum_d x*c*dsign[d%16]       (C0 is diagonal)
//     per 16-chunk wedge: 6 bivector comps from vector slots {1,2,4,8}
//   out = x + gate * ( sb*wedge_total  (+ ss*sum_s scalar_s at d==0) )

#define TT 4096
#define DD 1024

__device__ __forceinline__ float sigmf(float v) {
    return 1.0f / (1.0f + __expf(-v));
}

__global__ void __launch_bounds__(256, 4) clifford_kernel(
    const float* __restrict__ x,
    const float* __restrict__ gw,
    const float* __restrict__ gb,
    const float* __restrict__ sw,
    const float* __restrict__ bw,
    float* __restrict__ out)
{
    const int ty  = threadIdx.y;                    // 0..3 (row within block)
    const int ch  = threadIdx.x;                    // 0..63 (16-chunk within row)
    const int row = blockIdx.x * 4 + ty;            // global (b,t) row
    const int t   = row & (TT - 1);
    const int b   = row >> 12;                      // T = 2^12

    const size_t base = (size_t)row * DD + (size_t)ch * 16;

    // Load this row's chunk (16 floats = 4 x float4)
    const float4 xa = *(const float4*)(x + base +  0);   // d 0..3
    const float4 xb = *(const float4*)(x + base +  4);   // d 4..7
    const float4 xc = *(const float4*)(x + base +  8);   // d 8..11
    const float4 xd = *(const float4*)(x + base + 12);   // d 12..15

    // gate partial: dot with gate_w chunk
    const float4 ga = *(const float4*)(gw + ch * 16 +  0);
    const float4 gb4= *(const float4*)(gw + ch * 16 +  4);
    const float4 gc = *(const float4*)(gw + ch * 16 +  8);
    const float4 gd = *(const float4*)(gw + ch * 16 + 12);
    float gdot =
        xa.x*ga.x + xa.y*ga.y + xa.z*ga.z + xa.w*ga.w +
        xb.x*gb4.x + xb.y*gb4.y + xb.z*gb4.z + xb.w*gb4.w +
        xc.x*gc.x + xc.y*gc.y + xc.z*gc.z + xc.w*gc.w +
        xd.x*gd.x + xd.y*gd.y + xd.z*gd.z + xd.w*gd.w;

    // vector-grade slots of x: indices 1,2,4,8
    const float xv0 = xa.y, xv1 = xa.z, xv2 = xb.x, xv3 = xc.x;

    float scal = 0.0f;                 // sum over all 3 shifts (same gate, same ss)
    float w12 = 0.f, w13 = 0.f, w23 = 0.f, w14 = 0.f, w24 = 0.f, w34 = 0.f;

    const int rowb = b << 12;          // b * T

    #pragma unroll
    for (int si = 0; si < 3; si++) {
        const int s  = 1 << si;        // 1, 2, 4
        const int tm = (t - s) & (TT - 1);
        const size_t mbase = (size_t)(rowb + tm) * DD + (size_t)ch * 16;

        const float4 ma = *(const float4*)(x + mbase +  0);
        const float4 mb = *(const float4*)(x + mbase +  4);
        const float4 mc = *(const float4*)(x + mbase +  8);
        const float4 md = *(const float4*)(x + mbase + 12);

        // c = x - rolled
        const float c0  = xa.x - ma.x, c1  = xa.y - ma.y, c2  = xa.z - ma.z, c3  = xa.w - ma.w;
        const float c4  = xb.x - mb.x, c5  = xb.y - mb.y, c6  = xb.z - mb.z, c7  = xb.w - mb.w;
        const float c8  = xc.x - mc.x, c9  = xc.y - mc.y, c10 = xc.z - mc.z, c11 = xc.w - mc.w;
        const float c12 = xd.x - md.x, c13 = xd.y - md.y, c14 = xd.z - md.z, c15 = xd.w - md.w;

        // scalar part: diag signs d_i = (-1)^{k(k-1)/2} * (bit3 ? -1 : +1)
        // i:  0  1  2  3  4  5  6  7  8  9 10 11 12 13 14 15
        // d:  +  +  +  -  +  -  -  -  -  +  +  +  +  +  +  -
        scal += ( xa.x*c0 + xa.y*c1 + xa.z*c2 - xa.w*c3
                + xb.x*c4 - xb.y*c5 - xb.z*c6 - xb.w*c7
                - xc.x*c8 + xc.y*c9 + xc.z*c10 + xc.w*c11
                + xd.x*c12 + xd.y*c13 + xd.z*c14 - xd.w*c15);

        // wedge of vector parts: cv slots at indices 1,2,4,8
        const float cv0 = c1, cv1 = c2, cv2 = c4, cv3 = c8;
        w12 += xv0*cv1 - xv1*cv0;   // blade e12 -> index 3
        w13 += xv0*cv2 - xv2*cv0;   // blade e13 -> index 5
        w23 += xv1*cv2 - xv2*cv1;   // blade e23 -> index 6
        w14 += xv0*cv3 - xv3*cv0;   // blade e14 -> index 9
        w24 += xv1*cv3 - xv3*cv1;   // blade e24 -> index 10
        w34 += xv2*cv3 - xv3*cv2;   // blade e34 -> index 12
    }

    // Reduce gdot and scal across the 64 threads of this row (2 warps).
    #pragma unroll
    for (int o = 16; o > 0; o >>= 1) {
        gdot += __shfl_down_sync(0xffffffffu, gdot, o);
        scal += __shfl_down_sync(0xffffffffu, scal, o);
    }
    __shared__ float sg[4][2];
    __shared__ float ss_[4][2];
    const int wi = ch >> 5;            // warp within row: 0 or 1
    if ((ch & 31) == 0) { sg[ty][wi] = gdot; ss_[ty][wi] = scal; }
    __syncthreads();
    const float gtot = sg[ty][0] + sg[ty][1];
    const float stot = ss_[ty][0] + ss_[ty][1];

    const float gate = sigmf(gtot + gb[0]);
    const float ssv  = sigmf(sw[0]);
    const float sbv  = sigmf(bw[0]);
    const float gsb  = gate * sbv;

    float4 oa = xa, ob = xb, oc = xc, od = xd;
    oa.w += gsb * w12;    // index 3
    ob.y += gsb * w13;    // index 5
    ob.z += gsb * w23;    // index 6
    oc.y += gsb * w14;    // index 9
    oc.z += gsb * w24;    // index 10
    od.x += gsb * w34;    // index 12
    if (ch == 0) oa.x += gate * ssv * stot;   // scalar part lives at d == 0

    *(float4*)(out + base +  0) = oa;
    *(float4*)(out + base +  4) = ob;
    *(float4*)(out + base +  8) = oc;
    *(float4*)(out + base + 12) = od;
}

extern "C" void kernel_launch(void* const* d_in, const int* in_sizes, int n_in,
                              void* d_out, int out_size) {
    const float* x  = (const float*)d_in[0];
    const float* gw = (const float*)d_in[1];
    const float* gb = (const float*)d_in[2];
    const float* sw = (const float*)d_in[3];
    const float* bw = (const float*)d_in[4];
    float* out = (float*)d_out;

    const int B    = in_sizes[0] / (TT * DD);
    const int rows = B * TT;
    dim3 blk(64, 4, 1);
    clifford_kernel<<<rows / 4, blk>>>(x, gw, gb, sw, bw, out);
}

// round 4
// speedup vs baseline: 1.2120x; 1.2120x over previous
#include <cuda_runtime.h>

// CliffordInteractionExpert — dense-layout streaming kernel.
// Layout: 256 threads per block = one row of D=1024 floats, one float4 per
// thread (fully dense/coalesced loads & stores). A 16-float Clifford chunk
// spans 4 adjacent lanes (p = tid&3 = quad-in-chunk); wedge cross-terms are
// exchanged with width-4 shuffles.
// Each block walks a strip of STRIP=64 consecutive t values in groups of 8,
// keeping the last 4 rows in registers so shifted rows (t-1,t-2,t-4) never
// touch the memory system again.

#define TT 4096
#define DD 1024
#define STRIP 64

__device__ __forceinline__ float sigmf(float v) {
    return 1.0f / (1.0f + __expf(-v));
}

__device__ __forceinline__ void shift_accum(
    const float4 xc, const float4 m, const float4 xs,
    float xv0, float xv1, float xv2, float xv3,
    float& sc, float& w12, float& w13, float& w23,
    float& w14, float& w24, float& w34)
{
    // c = x - rolled (this thread's quad)
    const float c0 = xc.x - m.x;
    const float c1 = xc.y - m.y;
    const float c2 = xc.z - m.z;
    const float c3 = xc.w - m.w;
    // scalar part (signs pre-folded into xs)
    sc += xs.x * c0 + xs.y * c1 + xs.z * c2 + xs.w * c3;
    // vector components of c: d1,d2 live on p==0 lane (c1,c2); d4 on p==1 (c0); d8 on p==2 (c0)
    const float cv0 = __shfl_sync(0xffffffffu, c1, 0, 4);
    const float cv1 = __shfl_sync(0xffffffffu, c2, 0, 4);
    const float cv2 = __shfl_sync(0xffffffffu, c0, 1, 4);
    const float cv3 = __shfl_sync(0xffffffffu, c0, 2, 4);
    w12 += xv0 * cv1 - xv1 * cv0;
    w13 += xv0 * cv2 - xv2 * cv0;
    w23 += xv1 * cv2 - xv2 * cv1;
    w14 += xv0 * cv3 - xv3 * cv0;
    w24 += xv1 * cv3 - xv3 * cv1;
    w34 += xv2 * cv3 - xv3 * cv2;
}

__global__ void __launch_bounds__(256, 2) clifford_stream(
    const float* __restrict__ x,
    const float* __restrict__ gw,
    const float* __restrict__ gb,
    const float* __restrict__ sw,
    const float* __restrict__ bw,
    float* __restrict__ out)
{
    const int tid = threadIdx.x;          // 0..255  = quad index within row
    const int p   = tid & 3;              // quad within 16-float chunk
    const int bid = blockIdx.x;
    const int b   = bid >> 6;             // 64 strips per batch (4096/64)
    const int t0  = (bid & 63) * STRIP;

    const float* xrow = x   + (size_t)b * TT * DD + tid * 4;
    float*       orow = out + (size_t)b * TT * DD + tid * 4;

    // gate weights for this quad (stays in regs for the whole strip)
    const float4 gq  = *(const float4*)(gw + tid * 4);
    const float  gbv = __ldg(gb);
    const float  ssv = sigmf(__ldg(sw));
    const float  sbv = sigmf(__ldg(bw));

    // diag signs of C0 per position within chunk (d%16 = 4p+i):
    // p0: + + + -   p1: + - - -   p2: - + + +   p3: + + + -
    float4 sg;
    sg.x = (p == 2) ? -1.f : 1.f;
    sg.y = (p == 1) ? -1.f : 1.f;
    sg.z = sg.y;
    sg.w = (p == 2) ?  1.f : -1.f;

    const float fxw = (p == 0) ? 1.f : 0.f;              // w12 -> .w
    const float fyz = (p == 1 || p == 2) ? 1.f : 0.f;    // w13/w14 -> .y, w23/w24 -> .z
    const float fx3 = (p == 3) ? 1.f : 0.f;              // w34 -> .x
    const float f00 = (tid == 0) ? 1.f : 0.f;            // scalar part -> d==0

    // rows t-1..t-4 relative to current group start
    float4 prev[4];
    #pragma unroll
    for (int k = 0; k < 4; k++) {
        const int tr = (t0 - 4 + k) & (TT - 1);          // circular roll
        prev[k] = *(const float4*)(xrow + (size_t)tr * DD);
    }

    __shared__ float2 red[2][8][8];       // [group parity][row j][warp] = (gdot, scal)

    float wstA[8], wstB[8];

    for (int g = 0; g < STRIP / 8; ++g) {
        const int Tb  = t0 + g * 8;
        const int par = g & 1;

        // batch-load 8 rows (8 independent dense LDG.128 per thread)
        float4 cur[8];
        #pragma unroll
        for (int j = 0; j < 8; j++)
            cur[j] = *(const float4*)(xrow + (size_t)(Tb + j) * DD);

        #pragma unroll
        for (int j = 0; j < 8; j++) {
            const float4 xc = cur[j];
            const float4 m1 = (j < 1) ? prev[3]     : cur[(j - 1) & 7];
            const float4 m2 = (j < 2) ? prev[2 + j] : cur[(j - 2) & 7];
            const float4 m4 = (j < 4) ? prev[j & 3] : cur[(j - 4) & 7];

            float gd = xc.x * gq.x + xc.y * gq.y + xc.z * gq.z + xc.w * gq.w;
            float4 xs;
            xs.x = xc.x * sg.x; xs.y = xc.y * sg.y;
            xs.z = xc.z * sg.z; xs.w = xc.w * sg.w;

            // vector components of x for this chunk (broadcast within 4-lane group)
            const float xv0 = __shfl_sync(0xffffffffu, xc.y, 0, 4);
            const float xv1 = __shfl_sync(0xffffffffu, xc.z, 0, 4);
            const float xv2 = __shfl_sync(0xffffffffu, xc.x, 1, 4);
            const float xv3 = __shfl_sync(0xffffffffu, xc.x, 2, 4);

            float sc = 0.f, w12 = 0.f, w13 = 0.f, w23 = 0.f,
                  w14 = 0.f, w24 = 0.f, w34 = 0.f;
            shift_accum(xc, m1, xs, xv0, xv1, xv2, xv3, sc, w12, w13, w23, w14, w24, w34);
            shift_accum(xc, m2, xs, xv0, xv1, xv2, xv3, sc, w12, w13, w23, w14, w24, w34);
            shift_accum(xc, m4, xs, xv0, xv1, xv2, xv3, sc, w12, w13, w23, w14, w24, w34);

            // warp butterfly for gate dot and scalar part
            #pragma unroll
            for (int o = 16; o > 0; o >>= 1) {
                gd += __shfl_xor_sync(0xffffffffu, gd, o);
                sc += __shfl_xor_sync(0xffffffffu, sc, o);
            }
            if ((tid & 31) == 0) red[par][j][tid >> 5] = make_float2(gd, sc);

            // per-lane relevant wedge values
            wstA[j] = (p == 0) ? w12 : (p == 1) ? w13 : (p == 2) ? w14 : w34;
            wstB[j] = (p == 1) ? w23 : w24;
        }

        __syncthreads();

        #pragma unroll
        for (int j = 0; j < 8; j++) {
            float gtot = 0.f, stot = 0.f;
            #pragma unroll
            for (int w = 0; w < 8; w++) {
                const float2 r = red[par][j][w];
                gtot += r.x; stot += r.y;
            }
            const float gate = sigmf(gtot + gbv);
            const float gsb  = gate * sbv;

            float4 o = cur[j];
            const float A  = gsb * wstA[j];
            const float Bv = gsb * wstB[j];
            o.x += A * fx3 + gate * ssv * stot * f00;   // w34 @ idx12 lane / scalar @ d0
            o.y += A * fyz;                              // w13 / w14
            o.z += Bv * fyz;                             // w23 / w24
            o.w += A * fxw;                              // w12
            *(float4*)(orow + (size_t)(Tb + j) * DD) = o;
        }

        // slide window: last 4 rows of this group become prev
        #pragma unroll
        for (int k = 0; k < 4; k++) prev[k] = cur[4 + k];
    }
}

extern "C" void kernel_launch(void* const* d_in, const int* in_sizes, int n_in,
                              void* d_out, int out_size) {
    const float* x  = (const float*)d_in[0];
    const float* gw = (const float*)d_in[1];
    const float* gb = (const float*)d_in[2];
    const float* sw = (const float*)d_in[3];
    const float* bw = (const float*)d_in[4];
    float* out = (float*)d_out;

    const int B      = in_sizes[0] / (TT * DD);
    const int blocks = B * (TT / STRIP);     // 512 for B=8
    clifford_stream<<<blocks, 256>>>(x, gw, gb, sw, bw, out);
}

// round 8
// speedup vs baseline: 1.9577x; 1.6152x over previous
#include <cuda_runtime.h>

// CliffordInteractionExpert — fused-shift streaming kernel.
// Key identity: scalar & wedge are linear in c and share x across shifts:
//   sum_s f(x, x - roll(x,s)) = f(x, 3x - m1 - m2 - m4)
// Layout: 256 threads = one row (D=1024), one float4/thread; a 16-float
// Clifford chunk spans 4 lanes (p = tid&3). Blocks stream strips of t in
// groups of 8 rows, register window holds the last 4 rows.

#define TT 4096
#define DD 1024
#define FULL 0xffffffffu

__device__ __forceinline__ float sigmf(float v) {
    return 1.0f / (1.0f + __expf(-v));
}

__global__ void __launch_bounds__(256, 2) clifford_fused(
    const float* __restrict__ x,
    const float* __restrict__ gw,
    const float* __restrict__ gb,
    const float* __restrict__ sw,
    const float* __restrict__ bw,
    float* __restrict__ out)
{
    const int tid  = threadIdx.x;
    const int lane = tid & 31;
    const int warp = tid >> 5;
    const int p    = tid & 3;

    // 74 strips per batch, grid = B*74 = 592 = exactly 2 waves at occ 2.
    // Strips s<68: 7 groups (56 rows); s>=68: 6 groups (48 rows).
    const int bid = blockIdx.x;
    const int b   = bid / 74;
    const int s   = bid - b * 74;
    const int ng  = (s < 68) ? 7 : 6;
    const int t0  = 8 * (6 * s + (s < 68 ? s : 68));

    const float* xrow = x   + (size_t)b * TT * DD + tid * 4;
    float*       orow = out + (size_t)b * TT * DD + tid * 4;

    const float4 gq  = *(const float4*)(gw + tid * 4);
    const float  gbv = __ldg(gb);
    const float  ssv = sigmf(__ldg(sw));
    const float  sbv = sigmf(__ldg(bw));

    // C0 diagonal signs per quad position p
    float4 sg;
    sg.x = (p == 2) ? -1.f : 1.f;
    sg.y = (p == 1) ? -1.f : 1.f;
    sg.z = sg.y;
    sg.w = (p == 2) ?  1.f : -1.f;

    // wedge shuffle source lanes (within width-4 groups), constant per lane
    const int aSrc = (p == 3) ? 1 : 0;
    const int gSrc = (p == 0) ? 0 : ((p == 1) ? 1 : 2);
    const int dSrc = (p == 3) ? 1 : 0;

    // output placement masks
    const float fxw = (p == 0) ? 1.f : 0.f;
    const float fyz = (p == 1 || p == 2) ? 1.f : 0.f;
    const float fx3 = (p == 3) ? 1.f : 0.f;
    const float f00 = (tid == 0) ? 1.f : 0.f;

    // sliding window: rows t-4..t-1
    float4 prev[4];
    #pragma unroll
    for (int k = 0; k < 4; k++) {
        const int tr = (t0 - 4 + k) & (TT - 1);
        prev[k] = *(const float4*)(xrow + (size_t)tr * DD);
    }

    __shared__ float  part[16][9];   // [value][warp], padded for banks
    __shared__ float2 bcast[8];      // per-row (gate*sb, gate*ss*stot)

    for (int g = 0; g < ng; ++g) {
        const int Tb = t0 + g * 8;

        float4 cur[8];
        #pragma unroll
        for (int j = 0; j < 8; j++)
            cur[j] = *(const float4*)(xrow + (size_t)(Tb + j) * DD);

        float gd[8], sc[8], wA[8], wB[8];

        #pragma unroll
        for (int j = 0; j < 8; j++) {
            const float4 xc = cur[j];
            const float4 m1 = (j < 1) ? prev[3]     : cur[(j - 1) & 7];
            const float4 m2 = (j < 2) ? prev[2 + j] : cur[(j - 2) & 7];
            const float4 m4 = (j < 4) ? prev[j & 3] : cur[(j - 4) & 7];

            // fused c = 3x - (m1+m2+m4)
            float4 c;
            c.x = fmaf(3.f, xc.x, -(m1.x + m2.x + m4.x));
            c.y = fmaf(3.f, xc.y, -(m1.y + m2.y + m4.y));
            c.z = fmaf(3.f, xc.z, -(m1.z + m2.z + m4.z));
            c.w = fmaf(3.f, xc.w, -(m1.w + m2.w + m4.w));

            // gate partial
            gd[j] = xc.x * gq.x + xc.y * gq.y + xc.z * gq.z + xc.w * gq.w;
            // scalar partial (C0 diagonal)
            sc[j] = (xc.x * sg.x) * c.x + (xc.y * sg.y) * c.y
                  + (xc.z * sg.z) * c.z + (xc.w * sg.w) * c.w;

            // wedge: lane-targeted operand delivery (6 shfl)
            const float sendA = (p == 0) ? xc.y : xc.x;
            const float sendG = (p == 0) ? c.z  : c.x;
            const float sendB = (p == 0) ? xc.z : xc.x;
            const float sendD = (p == 0) ? c.y  : c.x;
            const float al = __shfl_sync(FULL, sendA, aSrc, 4);
            const float ga = __shfl_sync(FULL, sendG, gSrc, 4);
            const float be = __shfl_sync(FULL, sendB, gSrc, 4);
            const float de = __shfl_sync(FULL, sendD, dSrc, 4);
            const float ep = __shfl_sync(FULL, xc.z, 0, 4);
            const float ze = __shfl_sync(FULL, c.z, 0, 4);
            // p0: w12   p1: w13   p2: w14   p3: w34
            wA[j] = al * ga - be * de;
            // p1: w23   p2: w24   (unused on p0/p3)
            wB[j] = ep * ga - be * ze;
        }

        // folded reduction of 16 values {gd[0..7], sc[0..7]} over 32 lanes: 31 shfl
        {
            #pragma unroll
            for (int k = 0; k < 8; k++) gd[k] += __shfl_xor_sync(FULL, gd[k], 16);
            #pragma unroll
            for (int k = 0; k < 8; k++) sc[k] += __shfl_xor_sync(FULL, sc[k], 16);
            float a8[8];
            #pragma unroll
            for (int k = 0; k < 8; k++) {
                a8[k] = (lane & 16) ? sc[k] : gd[k];
                a8[k] += __shfl_xor_sync(FULL, a8[k], 8);
            }
            float a4[4];
            #pragma unroll
            for (int k = 0; k < 4; k++) {
                a4[k] = (lane & 8) ? a8[k + 4] : a8[k];
                a4[k] += __shfl_xor_sync(FULL, a4[k], 4);
            }
            float a2[2];
            #pragma unroll
            for (int k = 0; k < 2; k++) {
                a2[k] = (lane & 4) ? a4[k + 2] : a4[k];
                a2[k] += __shfl_xor_sync(FULL, a2[k], 2);
            }
            float a1 = (lane & 2) ? a2[1] : a2[0];
            a1 += __shfl_xor_sync(FULL, a1, 1);
            // lane l holds value k = bit4*8 + bit3*4 + bit2*2 + bit1 = (l>>1)&15
            if (!(lane & 1)) part[(lane >> 1) & 15][warp] = a1;
        }

        __syncthreads();

        if (tid < 8) {   // per-row gate & scalar, computed once
            float gdt = 0.f, sct = 0.f;
            #pragma unroll
            for (int w = 0; w < 8; w++) {
                gdt += part[tid][w];
                sct += part[tid + 8][w];
            }
            const float gate = sigmf(gdt + gbv);
            bcast[tid] = make_float2(gate * sbv, gate * ssv * sct);
        }

        __syncthreads();

        #pragma unroll
        for (int j = 0; j < 8; j++) {
            const float2 gg = bcast[j];      // (gate*sb, gate*ss*stot)
            float4 o = cur[j];
            const float A = gg.x * wA[j];
            const float Bv = gg.x * wB[j];
            o.x = fmaf(A, fx3, fmaf(gg.y, f00, o.x));   // w34 @p3 / scalar @d0
            o.y = fmaf(A, fyz, o.y);                     // w13 / w14
            o.z = fmaf(Bv, fyz, o.z);                    // w23 / w24
            o.w = fmaf(A, fxw, o.w);                     // w12
            *(float4*)(orow + (size_t)(Tb + j) * DD) = o;
        }

        #pragma unroll
        for (int k = 0; k < 4; k++) prev[k] = cur[4 + k];
    }
}

extern "C" void kernel_launch(void* const* d_in, const int* in_sizes, int n_in,
                              void* d_out, int out_size) {
    const float* x  = (const float*)d_in[0];
    const float* gw = (const float*)d_in[1];
    const float* gb = (const float*)d_in[2];
    const float* sw = (const float*)d_in[3];
    const float* bw = (const float*)d_in[4];
    float* out = (float*)d_out;

    const int B = in_sizes[0] / (TT * DD);
    clifford_fused<<<B * 74, 256>>>(x, gw, gb, sw, bw, out);
}